// round 12
// baseline (speedup 1.0000x reference)
#include <cuda_runtime.h>
#include <cstdint>

// out[dst[e], :] += w[e] * x[src[e], :]
// Fixed-capacity dst-binning + per-node register-accumulated gather.
// Gather: 2 nodes per warp (16-lane halves), float4 per lane, 4-edge unroll
// (MLP=4), and bin slots store PRE-SCALED src offsets (src*64 floats) so the
// per-edge address math is a single add.

static constexpr int F = 64;
static constexpr int THREADS = 256;
static constexpr int N_MAX = 1 << 17;       // 131072 >= 100000
static constexpr int E_MAX = 1 << 21;       // 2M >= 1M
static constexpr int MAX_DEG = 64;          // Poisson(10) tail safety

__device__ int g_cursor[N_MAX + 1];                          // [N] = overflow count
__device__ unsigned long long g_sw[(size_t)N_MAX * MAX_DEG]; // packed (w<<32)|(src*F)
__device__ int g_ovf[4096];                                  // overflowed edge ids

// ---------- 1. bin edges by dst (4 edges/thread, int4 loads; src pre-scaled) ----------
__global__ void __launch_bounds__(THREADS)
k_binplace(const float* __restrict__ ew, const int* __restrict__ ei, int E, int N)
{
    int t = blockIdx.x * THREADS + threadIdx.x;
    int quads = E >> 2;
    if (t < quads) {
        int e0 = t * 4;
        int4   s4 = __ldcs(reinterpret_cast<const int4*>(ei + e0));
        int4   d4 = __ldcs(reinterpret_cast<const int4*>(ei + E + e0));
        float4 w4 = __ldcs(reinterpret_cast<const float4*>(ew + e0));
        #pragma unroll
        for (int k = 0; k < 4; k++) {
            int s = (k == 0) ? s4.x : (k == 1) ? s4.y : (k == 2) ? s4.z : s4.w;
            int d = (k == 0) ? d4.x : (k == 1) ? d4.y : (k == 2) ? d4.z : d4.w;
            float w = (k == 0) ? w4.x : (k == 1) ? w4.y : (k == 2) ? w4.z : w4.w;
            int c = atomicAdd(&g_cursor[d], 1);
            if (c < MAX_DEG)
                g_sw[(size_t)d * MAX_DEG + c] =
                    ((unsigned long long)__float_as_uint(w) << 32) | (unsigned int)(s * F);
            else {
                int o = atomicAdd(&g_cursor[N], 1);
                if (o < 4096) g_ovf[o] = e0 + k;
            }
        }
    } else {
        int e = quads * 4 + (t - quads);
        if (e < E) {
            int s = __ldg(&ei[e]);
            int d = __ldg(&ei[E + e]);
            float w = __ldg(&ew[e]);
            int c = atomicAdd(&g_cursor[d], 1);
            if (c < MAX_DEG)
                g_sw[(size_t)d * MAX_DEG + c] =
                    ((unsigned long long)__float_as_uint(w) << 32) | (unsigned int)(s * F);
            else {
                int o = atomicAdd(&g_cursor[N], 1);
                if (o < 4096) g_ovf[o] = e;
            }
        }
    }
}

// ---------- 2. gather: 2 nodes/warp, float4/lane, 4-edge unroll ----------
__global__ void __launch_bounds__(THREADS)
k_gather(const float* __restrict__ x, const float* __restrict__ ew,
         const int* __restrict__ ei, float* __restrict__ out, int N, int E, int nb)
{
    if (blockIdx.x == (unsigned)nb) {
        // Overflow fallback: reads only; state reset by next replay's memset.
        int novf = g_cursor[N];
        if (novf > 4096) novf = 4096;
        int n = novf * 16;
        for (int i = threadIdx.x; i < n; i += THREADS) {
            int e = g_ovf[i >> 4];
            int c = i & 15;
            int   s = __ldg(&ei[e]);
            int   d = __ldg(&ei[E + e]);
            float w = __ldg(&ew[e]);
            float4 v = __ldg(reinterpret_cast<const float4*>(x + (long long)s * F + c * 4));
            v.x *= w; v.y *= w; v.z *= w; v.w *= w;
            float* dp = out + (long long)d * F + c * 4;
            asm volatile("red.global.add.v4.f32 [%0], {%1, %2, %3, %4};"
                         :: "l"(dp), "f"(v.x), "f"(v.y), "f"(v.z), "f"(v.w) : "memory");
        }
        return;
    }

    int gwarp = (blockIdx.x * THREADS + threadIdx.x) >> 5;   // warp id
    int half  = (threadIdx.x >> 4) & 1;                      // which node in warp
    int node  = gwarp * 2 + half;
    int l16   = threadIdx.x & 15;

    int deg = 0;
    if (node < N) deg = g_cursor[node];
    if (deg > MAX_DEG) deg = MAX_DEG;
    const unsigned long long* sw = g_sw + (size_t)node * MAX_DEG;

    int dmax = max(deg, __shfl_xor_sync(0xffffffffu, deg, 16));

    float4 acc = make_float4(0.f, 0.f, 0.f, 0.f);
    const float* xl = x + l16 * 4;                           // lane-fixed base

    int j = 0;
    for (; j + 4 <= dmax; j += 4) {
        ulonglong2 p0, p1;
        p0.x = p0.y = p1.x = p1.y = 0;
        bool a0 = (j     < deg);
        bool a2 = (j + 2 < deg);
        if (a0) p0 = __ldcs(reinterpret_cast<const ulonglong2*>(sw + j));
        if (a2) p1 = __ldcs(reinterpret_cast<const ulonglong2*>(sw + j + 2));

        unsigned o0 = (unsigned)p0.x, o1 = (unsigned)p0.y;
        unsigned o2 = (unsigned)p1.x, o3 = (unsigned)p1.y;
        float w0 = __uint_as_float((unsigned)(p0.x >> 32));
        float w1 = __uint_as_float((unsigned)(p0.y >> 32));
        float w2 = __uint_as_float((unsigned)(p1.x >> 32));
        float w3 = __uint_as_float((unsigned)(p1.y >> 32));

        // Front-batched independent row loads (MLP=4), predicated per edge.
        float4 v0 = make_float4(0,0,0,0), v1 = v0, v2 = v0, v3 = v0;
        if (a0)          v0 = __ldg(reinterpret_cast<const float4*>(xl + o0));
        if (j + 1 < deg) v1 = __ldg(reinterpret_cast<const float4*>(xl + o1));
        if (a2)          v2 = __ldg(reinterpret_cast<const float4*>(xl + o2));
        if (j + 3 < deg) v3 = __ldg(reinterpret_cast<const float4*>(xl + o3));

        acc.x += w0 * v0.x; acc.y += w0 * v0.y; acc.z += w0 * v0.z; acc.w += w0 * v0.w;
        acc.x += w1 * v1.x; acc.y += w1 * v1.y; acc.z += w1 * v1.z; acc.w += w1 * v1.w;
        acc.x += w2 * v2.x; acc.y += w2 * v2.y; acc.z += w2 * v2.z; acc.w += w2 * v2.w;
        acc.x += w3 * v3.x; acc.y += w3 * v3.y; acc.z += w3 * v3.z; acc.w += w3 * v3.w;
    }
    for (; j < dmax; j++) {
        if (j < deg) {
            unsigned long long a = __ldcs(&sw[j]);
            unsigned o = (unsigned)a;
            float w = __uint_as_float((unsigned)(a >> 32));
            float4 v = __ldg(reinterpret_cast<const float4*>(xl + o));
            acc.x += w * v.x; acc.y += w * v.y; acc.z += w * v.z; acc.w += w * v.w;
        }
    }

    if (node < N)
        *reinterpret_cast<float4*>(out + (long long)node * F + l16 * 4) = acc;
}

extern "C" void kernel_launch(void* const* d_in, const int* in_sizes, int n_in,
                              void* d_out, int out_size)
{
    const float* x  = (const float*)d_in[0];
    const float* ew = (const float*)d_in[1];
    const int*   ei = (const int*)d_in[2];
    float* out = (float*)d_out;

    int E = in_sizes[2] / 2;
    int N = out_size / F;
    if (E > E_MAX || N > N_MAX) return;   // fixed problem: E=1M, N=100k

    void* cur_addr = nullptr;
    cudaGetSymbolAddress(&cur_addr, g_cursor);
    cudaMemsetAsync(cur_addr, 0, (size_t)(N + 1) * sizeof(int), 0);

    int bin_threads = (E >> 2) + (E & 3);
    k_binplace<<<(bin_threads + THREADS - 1) / THREADS, THREADS>>>(ew, ei, E, N);

    int warps = (N + 1) / 2;                       // 2 nodes per warp
    int nb = (warps * 32 + THREADS - 1) / THREADS; // node blocks
    k_gather<<<nb + 1, THREADS>>>(x, ew, ei, out, N, E, nb);
}